// round 7
// baseline (speedup 1.0000x reference)
#include <cuda_runtime.h>
#include <math.h>

#define NU 50000
#define NI 40000
#define NN 90000
#define D  64
#define EH 500000
#define E  1000000
#define OD 192

// ------------------- scratch (static device globals; no allocation) -------------------
__device__ int   g_is64;           // 1 if edge_index is int64, 0 if int32
__device__ int   g_src[E];
__device__ int   g_dst[E];
__device__ int   g_degG[NN];       // in-degree over ei
__device__ int   g_offG[NN];
__device__ int   g_curG[NN];
__device__ int   g_csrG_src[E];    // src node per CSR slot
__device__ float g_e[E];           // exp(logit) per CSR slot (scratch per modality pass)
__device__ float g_alpha[2 * E];   // [mod*E + slot] final-GAT half-alpha
__device__ float g_wc[E];          // combined SAGE weight per CSR slot
__device__ __align__(16) float g_xm[2 * NN * D];  // per modality: rows 0..NU-1 pref, NU..NN-1 item feats
__device__ __align__(16) float g_hx[2 * NN * D];  // slot 0 = l2norm(id_emb), slot 1 = h1

__device__ __forceinline__ float lrelu(float v) { return v >= 0.f ? v : 0.01f * v; }
static inline int divup(int a, int b) { return (a + b - 1) / b; }

// ------------------- edge dtype sniff -------------------
// int64 little-endian node ids (< 2^31) have zero high words at odd int32 slots.
__global__ void k_sniff(const int* __restrict__ ei32) {
    int lane = threadIdx.x;           // 32 threads
    int nz = 0;
    for (int i = lane; i < 512; i += 32)
        if (ei32[2 * i + 1] != 0) nz++;
    #pragma unroll
    for (int o = 16; o; o >>= 1) nz += __shfl_xor_sync(0xffffffffu, nz, o);
    if (lane == 0) g_is64 = (nz == 0) ? 1 : 0;
}

// ------------------- graph construction -------------------
__global__ void k_zero() {
    int i = blockIdx.x * blockDim.x + threadIdx.x;
    if (i < NN) g_degG[i] = 0;
}

__global__ void k_build(const void* __restrict__ eiRaw) {
    int i = blockIdx.x * blockDim.x + threadIdx.x;
    if (i >= E) return;
    int s, d;
    if (g_is64) {
        const long long* e64 = (const long long*)eiRaw;
        s = (int)e64[i];
        d = (int)e64[E + i];
    } else {
        const int* e32 = (const int*)eiRaw;
        s = e32[i];
        d = e32[E + i];
    }
    if ((unsigned)s >= NN) s = 0;   // defensive: never trap on bad decode
    if ((unsigned)d >= NN) d = 0;
    g_src[i] = s;
    g_dst[i] = d;
    atomicAdd(&g_degG[d], 1);
}

// Single-block exclusive scan of degG -> offG/curG.
__global__ void k_scan() {
    __shared__ int sh[1024];
    __shared__ int run;
    int t = threadIdx.x;
    if (t == 0) run = 0;
    __syncthreads();
    for (int base = 0; base < NN; base += 1024) {
        int i = base + t;
        int v = (i < NN) ? g_degG[i] : 0;
        sh[t] = v;
        __syncthreads();
        for (int st = 1; st < 1024; st <<= 1) {
            int x = (t >= st) ? sh[t - st] : 0;
            __syncthreads();
            sh[t] += x;
            __syncthreads();
        }
        if (i < NN) {
            int o = run + sh[t] - v;
            g_offG[i] = o;
            g_curG[i] = o;
        }
        __syncthreads();
        if (t == 0) run += sh[1023];
        __syncthreads();
    }
}

__global__ void k_place() {
    int i = blockIdx.x * blockDim.x + threadIdx.x;
    if (i >= E) return;
    int p = atomicAdd(&g_curG[g_dst[i]], 1);
    if ((unsigned)p < E) g_csrG_src[p] = g_src[i];
}

// ------------------- dense ops -------------------
// xm[mod] item rows = leaky(A[NI,K] @ B[K,64] + bias). Tile 64x64, K-tile 64.
__global__ __launch_bounds__(256) void k_gemm_leaky(
    const float* __restrict__ A, const float* __restrict__ Bm,
    const float* __restrict__ bias, int mod, int K)
{
    float* C = g_xm + (size_t)mod * NN * D + (size_t)NU * D;
    __shared__ float sA[64][68];
    __shared__ float sB[64][68];
    int t  = threadIdx.x;
    int tx = t & 15;
    int ty = t >> 4;
    int m0 = blockIdx.x * 64;
    int lr = t >> 4;
    int lc = (t & 15) * 4;

    float acc[4][4] = {};
    for (int kt = 0; kt < K; kt += 64) {
        #pragma unroll
        for (int p = 0; p < 4; p++) {
            int r = lr + p * 16;
            float4 av = *(const float4*)&A[(size_t)(m0 + r) * K + kt + lc];
            *(float4*)&sA[r][lc] = av;
            float4 bv = *(const float4*)&Bm[(size_t)(kt + r) * 64 + lc];
            *(float4*)&sB[r][lc] = bv;
        }
        __syncthreads();
        #pragma unroll
        for (int k = 0; k < 64; k++) {
            float a0 = sA[ty * 4 + 0][k];
            float a1 = sA[ty * 4 + 1][k];
            float a2 = sA[ty * 4 + 2][k];
            float a3 = sA[ty * 4 + 3][k];
            float4 b = *(float4*)&sB[k][tx * 4];
            acc[0][0] += a0 * b.x; acc[0][1] += a0 * b.y; acc[0][2] += a0 * b.z; acc[0][3] += a0 * b.w;
            acc[1][0] += a1 * b.x; acc[1][1] += a1 * b.y; acc[1][2] += a1 * b.z; acc[1][3] += a1 * b.w;
            acc[2][0] += a2 * b.x; acc[2][1] += a2 * b.y; acc[2][2] += a2 * b.z; acc[2][3] += a2 * b.w;
            acc[3][0] += a3 * b.x; acc[3][1] += a3 * b.y; acc[3][2] += a3 * b.z; acc[3][3] += a3 * b.w;
        }
        __syncthreads();
    }
    float b0 = bias[tx * 4 + 0], b1 = bias[tx * 4 + 1], b2 = bias[tx * 4 + 2], b3 = bias[tx * 4 + 3];
    #pragma unroll
    for (int i = 0; i < 4; i++) {
        float4 o;
        o.x = lrelu(acc[i][0] + b0);
        o.y = lrelu(acc[i][1] + b1);
        o.z = lrelu(acc[i][2] + b2);
        o.w = lrelu(acc[i][3] + b3);
        *(float4*)&C[(size_t)(m0 + ty * 4 + i) * 64 + tx * 4] = o;
    }
}

// l2norm item-feature rows of xm[mod] in place (NI rows). Warp per row.
__global__ void k_l2norm_feat(int mod) {
    int row = blockIdx.x * 8 + (threadIdx.x >> 5);
    if (row >= NI) return;
    float* f = g_xm + (size_t)mod * NN * D + (size_t)(NU + row) * D;
    int lane = threadIdx.x & 31;
    float a = f[lane];
    float b = f[32 + lane];
    float ss = a * a + b * b;
    #pragma unroll
    for (int o = 16; o; o >>= 1) ss += __shfl_xor_sync(0xffffffffu, ss, o);
    float inv = rsqrtf(fmaxf(ss, 1e-24f));
    f[lane]      = a * inv;
    f[32 + lane] = b * inv;
}

// pref rows of xm[mod] = l2norm(input) (NU rows).
__global__ void k_l2norm_pref(const float* __restrict__ in, int mod) {
    int row = blockIdx.x * 8 + (threadIdx.x >> 5);
    if (row >= NU) return;
    float* p = g_xm + (size_t)mod * NN * D + (size_t)row * D;
    int lane = threadIdx.x & 31;
    float a = in[(size_t)row * 64 + lane];
    float b = in[(size_t)row * 64 + 32 + lane];
    float ss = a * a + b * b;
    #pragma unroll
    for (int o = 16; o; o >>= 1) ss += __shfl_xor_sync(0xffffffffu, ss, o);
    float inv = rsqrtf(fmaxf(ss, 1e-24f));
    p[lane]      = a * inv;
    p[32 + lane] = b * inv;
}

// g_hx slot0 = l2norm(id_emb) (NN rows).
__global__ void k_l2norm_x(const float* __restrict__ in) {
    int row = blockIdx.x * 8 + (threadIdx.x >> 5);
    if (row >= NN) return;
    int lane = threadIdx.x & 31;
    float a = in[(size_t)row * 64 + lane];
    float b = in[(size_t)row * 64 + 32 + lane];
    float ss = a * a + b * b;
    #pragma unroll
    for (int o = 16; o; o >>= 1) ss += __shfl_xor_sync(0xffffffffu, ss, o);
    float inv = rsqrtf(fmaxf(ss, 1e-24f));
    g_hx[(size_t)row * 64 + lane]      = a * inv;
    g_hx[(size_t)row * 64 + 32 + lane] = b * inv;
}

// ------------------- GAT (gather, warp per dst node) -------------------
__global__ void k_gat_node(int mod, int nNodes, int mode, float* __restrict__ out, int modoff) {
    int n = blockIdx.x * 8 + (threadIdx.x >> 5);
    if (n >= nNodes) return;
    float* xbase = g_xm + (size_t)mod * NN * D;
    int lane = threadIdx.x & 31;
    int beg = g_offG[n];
    int end = beg + g_degG[n];

    float2 xdv = *(const float2*)&xbase[(size_t)n * D + lane * 2];

    // pass 1: exp(dot) per edge, segment sum (rows unit-norm -> no max-subtract needed)
    float s = 0.f;
    for (int p = beg; p < end; p++) {
        int src = g_csrG_src[p];
        float2 v = *(const float2*)&xbase[(size_t)src * D + lane * 2];
        float dt = xdv.x * v.x + xdv.y * v.y;
        #pragma unroll
        for (int o = 16; o; o >>= 1) dt += __shfl_xor_sync(0xffffffffu, dt, o);
        float ex = __expf(dt);   // identical on all lanes
        if (lane == 0) g_e[p] = ex;
        s += ex;
    }
    __syncwarp();

    float accx = 0.f, accy = 0.f;
    if (mode == 0) {
        float invs = 1.f / (s + 1e-16f);
        for (int p = beg; p < end; p++) {
            int src = g_csrG_src[p];
            float2 v = *(const float2*)&xbase[(size_t)src * D + lane * 2];
            float a = g_e[p] * invs;
            accx += a * v.x;
            accy += a * v.y;
        }
        float nx = xdv.x + accx, ny = xdv.y + accy;
        float ss = nx * nx + ny * ny;
        #pragma unroll
        for (int o = 16; o; o >>= 1) ss += __shfl_xor_sync(0xffffffffu, ss, o);
        float inv = rsqrtf(fmaxf(ss, 1e-24f));
        xbase[(size_t)n * D + lane * 2]     = nx * inv;
        xbase[(size_t)n * D + lane * 2 + 1] = ny * inv;
    } else {
        float inv2 = 1.f / (2.f * s + 1e-16f);
        float* alpha = g_alpha + (size_t)mod * E;
        for (int p = beg; p < end; p++) {
            int src = g_csrG_src[p];
            float2 v = *(const float2*)&xbase[(size_t)src * D + lane * 2];
            float a = g_e[p] * inv2;
            if (lane == 0) alpha[p] = a;
            float a2 = a + a;                 // ei2 duplicates each directed edge
            accx += a2 * v.x;
            accy += a2 * v.y;
        }
        int c = lane * 2;
        out[(size_t)n * OD + 64 + modoff + c]     = xdv.x + lrelu(accx);
        out[(size_t)n * OD + 64 + modoff + c + 1] = xdv.y + lrelu(accy);
    }
}

// Combined SAGE weight per CSR slot (both ei2 copies share this value; 2x cancels vs cnt=2*degG).
__global__ void k_weight(const float* __restrict__ conf) {
    int p = blockIdx.x * blockDim.x + threadIdx.x;
    if (p >= E) return;
    int src = g_csrG_src[p];
    float wv = g_alpha[p];
    float wt = g_alpha[E + p];
    float w = fmaxf(fmaxf(wv * conf[2 * src], wt * conf[2 * src + 1]), 0.f);
    g_wc[p] = w;
}

// SAGE gather over GAT CSR. layer 1: hx slot0 -> hx slot1; layer 2: hx slot1 -> out[:,0:64].
__global__ void k_sage_node(int layer, float* __restrict__ out) {
    int n = blockIdx.x * 8 + (threadIdx.x >> 5);
    if (n >= NN) return;
    const float* xin = g_hx + (size_t)(layer - 1) * NN * D;
    int lane = threadIdx.x & 31;
    int beg = g_offG[n];
    int cnt = g_degG[n];
    float ax = 0.f, ay = 0.f;
    for (int p = beg; p < beg + cnt; p++) {
        float w = g_wc[p];
        if (w != 0.f) {
            int src = g_csrG_src[p];
            float2 v = *(const float2*)&xin[(size_t)src * D + lane * 2];
            ax += w * v.x;
            ay += w * v.y;
        }
    }
    float invd = 1.f / fmaxf((float)cnt, 1.f);
    float hx = lrelu(ax * invd), hy = lrelu(ay * invd);
    int c = lane * 2;
    if (layer == 1) {
        g_hx[(size_t)NN * D + (size_t)n * D + c]     = hx;
        g_hx[(size_t)NN * D + (size_t)n * D + c + 1] = hy;
    } else {
        size_t b = (size_t)n * D + c;
        out[(size_t)n * OD + c]     = g_hx[b]     + g_hx[(size_t)NN * D + b]     + hx;
        out[(size_t)n * OD + c + 1] = g_hx[b + 1] + g_hx[(size_t)NN * D + b + 1] + hy;
    }
}

// ------------------- launch -------------------
extern "C" void kernel_launch(void* const* d_in, const int* in_sizes, int n_in,
                              void* d_out, int out_size) {
    // Resolve inputs by element count (robust to metadata ordering).
    const void* ei = nullptr;
    const float *v_feat = 0, *t_feat = 0, *pref_v = 0, *pref_t = 0;
    const float *W_v = 0, *b_v = 0, *W_t = 0, *b_t = 0, *id_emb = 0, *conf = 0;
    for (int i = 0; i < n_in; i++) {
        long long sz = in_sizes[i];
        const void* p = d_in[i];
        switch (sz) {
            case 2000000LL:  ei = p; break;
            case 81920000LL: v_feat = (const float*)p; break;
            case 15360000LL: t_feat = (const float*)p; break;
            case 3200000LL:  if (!pref_v) pref_v = (const float*)p; else pref_t = (const float*)p; break;
            case 131072LL:   W_v = (const float*)p; break;
            case 24576LL:    W_t = (const float*)p; break;
            case 64LL:       if (!b_v) b_v = (const float*)p; else b_t = (const float*)p; break;
            case 5760000LL:  id_emb = (const float*)p; break;
            case 180000LL:   conf = (const float*)p; break;
            default: break;
        }
    }
    float* out = (float*)d_out;

    const int B = 256;
    const int gridNodeAll = divup(NN, 8);
    const int gridNodeU   = divup(NU, 8);

    // graph construction
    k_sniff<<<1, 32>>>((const int*)ei);
    k_zero <<<divup(NN, B), B>>>();
    k_build<<<divup(E, B), B>>>(ei);
    k_scan <<<1, 1024>>>();
    k_place<<<divup(E, B), B>>>();

    // content branches
    for (int mod = 0; mod < 2; mod++) {
        const float* feat_in = mod == 0 ? v_feat : t_feat;
        const float* W       = mod == 0 ? W_v : W_t;
        const float* bias    = mod == 0 ? b_v : b_t;
        const float* pref_in = mod == 0 ? pref_v : pref_t;
        int K = mod == 0 ? 2048 : 384;

        k_gemm_leaky<<<NI / 64, 256>>>(feat_in, W, bias, mod, K);
        k_l2norm_feat<<<divup(NI, 8), 256>>>(mod);
        k_l2norm_pref<<<divup(NU, 8), 256>>>(pref_in, mod);

        for (int it = 0; it < 3; it++)
            k_gat_node<<<gridNodeU, 256>>>(mod, NU, 0, nullptr, 0);

        k_gat_node<<<gridNodeAll, 256>>>(mod, NN, 1, out, mod * 64);
    }

    // SAGE weights per CSR slot
    k_weight<<<divup(E, B), B>>>(conf);

    // egcn
    k_l2norm_x<<<divup(NN, 8), 256>>>(id_emb);
    k_sage_node<<<gridNodeAll, 256>>>(1, nullptr);
    k_sage_node<<<gridNodeAll, 256>>>(2, out);
}

// round 8
// speedup vs baseline: 1.1450x; 1.1450x over previous
#include <cuda_runtime.h>
#include <math.h>

#define NU 50000
#define NI 40000
#define NN 90000
#define D  64
#define EH 500000
#define E  1000000
#define OD 192

typedef unsigned long long ull;

// ------------------- scratch (static device globals; no allocation) -------------------
__device__ int   g_is64;           // 1 if edge_index is int64, 0 if int32
__device__ int   g_src[E];
__device__ int   g_dst[E];
__device__ int   g_degG[NN];       // in-degree over ei
__device__ int   g_offG[NN];
__device__ int   g_curG[NN];
__device__ int   g_bsum[128];      // scan block sums
__device__ int   g_csrG_src[E];    // src node per CSR slot
__device__ float g_e[E];           // exp(logit) per CSR slot (scratch per modality pass)
__device__ float g_alpha[2 * E];   // [mod*E + slot] final-GAT half-alpha
__device__ float g_wc[E];          // combined SAGE weight per CSR slot
__device__ __align__(16) float g_xm[2 * NN * D];  // per modality: rows 0..NU-1 pref, NU..NN-1 item feats
__device__ __align__(16) float g_hx[2 * NN * D];  // slot 0 = l2norm(id_emb), slot 1 = h1

__device__ __forceinline__ float lrelu(float v) { return v >= 0.f ? v : 0.01f * v; }
static inline int divup(int a, int b) { return (a + b - 1) / b; }

__device__ __forceinline__ void ffma2(ull& d, ull a, ull b) {
    asm("fma.rn.f32x2 %0, %1, %2, %0;" : "+l"(d) : "l"(a), "l"(b));
}
__device__ __forceinline__ ull pack2(float lo, float hi) {
    ull r;
    asm("mov.b64 %0, {%1, %2};" : "=l"(r) : "f"(lo), "f"(hi));
    return r;
}
__device__ __forceinline__ float2 unpack2(ull v) {
    float2 r;
    asm("mov.b64 {%0, %1}, %2;" : "=f"(r.x), "=f"(r.y) : "l"(v));
    return r;
}

// ------------------- edge dtype sniff -------------------
__global__ void k_sniff(const int* __restrict__ ei32) {
    int lane = threadIdx.x;
    int nz = 0;
    for (int i = lane; i < 512; i += 32)
        if (ei32[2 * i + 1] != 0) nz++;
    #pragma unroll
    for (int o = 16; o; o >>= 1) nz += __shfl_xor_sync(0xffffffffu, nz, o);
    if (lane == 0) g_is64 = (nz == 0) ? 1 : 0;
}

// ------------------- graph construction -------------------
__global__ void k_zero() {
    int i = blockIdx.x * blockDim.x + threadIdx.x;
    if (i < NN) g_degG[i] = 0;
}

__global__ void k_build(const void* __restrict__ eiRaw) {
    int i = blockIdx.x * blockDim.x + threadIdx.x;
    if (i >= E) return;
    int s, d;
    if (g_is64) {
        const long long* e64 = (const long long*)eiRaw;
        s = (int)e64[i];
        d = (int)e64[E + i];
    } else {
        const int* e32 = (const int*)eiRaw;
        s = e32[i];
        d = e32[E + i];
    }
    if ((unsigned)s >= NN) s = 0;
    if ((unsigned)d >= NN) d = 0;
    g_src[i] = s;
    g_dst[i] = d;
    atomicAdd(&g_degG[d], 1);
}

// Hierarchical scan: 88 blocks x 1024 do local KS scans; block sums scanned; add-back.
__global__ void k_scan1() {
    __shared__ int sh[1024];
    int t = threadIdx.x;
    int i = blockIdx.x * 1024 + t;
    int v = (i < NN) ? g_degG[i] : 0;
    sh[t] = v;
    __syncthreads();
    for (int st = 1; st < 1024; st <<= 1) {
        int x = (t >= st) ? sh[t - st] : 0;
        __syncthreads();
        sh[t] += x;
        __syncthreads();
    }
    if (i < NN) g_offG[i] = sh[t] - v;   // block-local exclusive
    if (t == 1023) g_bsum[blockIdx.x] = sh[1023];
}

__global__ void k_scan2(int nb) {
    __shared__ int sh[128];
    int t = threadIdx.x;
    int v = (t < nb) ? g_bsum[t] : 0;
    sh[t] = v;
    __syncthreads();
    for (int st = 1; st < 128; st <<= 1) {
        int x = (t >= st) ? sh[t - st] : 0;
        __syncthreads();
        sh[t] += x;
        __syncthreads();
    }
    if (t < nb) g_bsum[t] = sh[t] - v;   // exclusive block offsets
}

__global__ void k_scan3() {
    int i = blockIdx.x * 1024 + threadIdx.x;
    if (i < NN) {
        int o = g_offG[i] + g_bsum[blockIdx.x];
        g_offG[i] = o;
        g_curG[i] = o;
    }
}

__global__ void k_place() {
    int i = blockIdx.x * blockDim.x + threadIdx.x;
    if (i >= E) return;
    int p = atomicAdd(&g_curG[g_dst[i]], 1);
    if ((unsigned)p < E) g_csrG_src[p] = g_src[i];
}

// ------------------- fused GEMM + bias + leaky + l2norm -------------------
// xm[mod] item rows = l2norm(leaky(A[NI,K] @ B[K,64] + bias)).
// Tile 128x64, K-tile 32. 256 threads; thread tile 8x4 via fma.rn.f32x2.
__global__ __launch_bounds__(256) void k_gemm_fused(
    const float* __restrict__ A, const float* __restrict__ Bm,
    const float* __restrict__ bias, int mod, int K)
{
    float* C = g_xm + (size_t)mod * NN * D + (size_t)NU * D;
    __shared__ __align__(16) float sA[32][132];   // [k][m], row stride 132 (16B-aligned rows)
    __shared__ __align__(16) float sB[32][68];    // [k][n]
    int t  = threadIdx.x;
    int tx = t & 15;          // n group (4 cols)
    int ty = t >> 4;          // m group (8 rows)
    int m0 = blockIdx.x * 128;

    // loader indices
    int ak4 = t & 7;          // A float4 col within K-tile (8 x 4 = 32 k)
    int ar  = t >> 3;         // A row 0..31 (+p*32)
    int bn4 = t & 15;         // B float4 col (16 x 4 = 64 n)
    int bkr = t >> 4;         // B k row 0..15 (+p*16)

    ull acc[4][4];            // [m-pair][n], each = {c[2mp][n], c[2mp+1][n]}
    #pragma unroll
    for (int i = 0; i < 4; i++)
        #pragma unroll
        for (int j = 0; j < 4; j++) acc[i][j] = 0ull;

    for (int kt = 0; kt < K; kt += 32) {
        #pragma unroll
        for (int p = 0; p < 4; p++) {
            int m = ar + p * 32;
            int gm = m0 + m;
            float4 av = make_float4(0.f, 0.f, 0.f, 0.f);
            if (gm < NI) av = *(const float4*)&A[(size_t)gm * K + kt + ak4 * 4];
            sA[ak4 * 4 + 0][m] = av.x;
            sA[ak4 * 4 + 1][m] = av.y;
            sA[ak4 * 4 + 2][m] = av.z;
            sA[ak4 * 4 + 3][m] = av.w;
        }
        #pragma unroll
        for (int p = 0; p < 2; p++) {
            int k = bkr + p * 16;
            *(float4*)&sB[k][bn4 * 4] = *(const float4*)&Bm[(size_t)(kt + k) * 64 + bn4 * 4];
        }
        __syncthreads();
        #pragma unroll
        for (int k = 0; k < 32; k++) {
            const ull* pa = (const ull*)&sA[k][ty * 8];
            ull a0 = pa[0], a1 = pa[1], a2 = pa[2], a3 = pa[3];
            float4 b = *(float4*)&sB[k][tx * 4];
            ull bs0 = pack2(b.x, b.x);
            ull bs1 = pack2(b.y, b.y);
            ull bs2 = pack2(b.z, b.z);
            ull bs3 = pack2(b.w, b.w);
            ffma2(acc[0][0], a0, bs0); ffma2(acc[0][1], a0, bs1); ffma2(acc[0][2], a0, bs2); ffma2(acc[0][3], a0, bs3);
            ffma2(acc[1][0], a1, bs0); ffma2(acc[1][1], a1, bs1); ffma2(acc[1][2], a1, bs2); ffma2(acc[1][3], a1, bs3);
            ffma2(acc[2][0], a2, bs0); ffma2(acc[2][1], a2, bs1); ffma2(acc[2][2], a2, bs2); ffma2(acc[2][3], a2, bs3);
            ffma2(acc[3][0], a3, bs0); ffma2(acc[3][1], a3, bs1); ffma2(acc[3][2], a3, bs2); ffma2(acc[3][3], a3, bs3);
        }
        __syncthreads();
    }

    // epilogue: bias + leaky + row l2norm (16 lanes x 4 cols = full 64-col row)
    float b4[4];
    #pragma unroll
    for (int j = 0; j < 4; j++) b4[j] = bias[tx * 4 + j];

    #pragma unroll
    for (int mp = 0; mp < 4; mp++) {
        float clo[4], chi[4];
        #pragma unroll
        for (int j = 0; j < 4; j++) {
            float2 v = unpack2(acc[mp][j]);
            clo[j] = lrelu(v.x + b4[j]);
            chi[j] = lrelu(v.y + b4[j]);
        }
        float sl = clo[0]*clo[0] + clo[1]*clo[1] + clo[2]*clo[2] + clo[3]*clo[3];
        float sh2 = chi[0]*chi[0] + chi[1]*chi[1] + chi[2]*chi[2] + chi[3]*chi[3];
        #pragma unroll
        for (int o = 1; o < 16; o <<= 1) {
            sl  += __shfl_xor_sync(0xffffffffu, sl,  o);
            sh2 += __shfl_xor_sync(0xffffffffu, sh2, o);
        }
        float il = rsqrtf(fmaxf(sl,  1e-24f));
        float ih = rsqrtf(fmaxf(sh2, 1e-24f));
        int rl = m0 + ty * 8 + mp * 2;
        if (rl < NI) {
            float4 o4 = make_float4(clo[0]*il, clo[1]*il, clo[2]*il, clo[3]*il);
            *(float4*)&C[(size_t)rl * 64 + tx * 4] = o4;
        }
        if (rl + 1 < NI) {
            float4 o4 = make_float4(chi[0]*ih, chi[1]*ih, chi[2]*ih, chi[3]*ih);
            *(float4*)&C[(size_t)(rl + 1) * 64 + tx * 4] = o4;
        }
    }
}

// pref rows of xm[mod] = l2norm(input) (NU rows).
__global__ void k_l2norm_pref(const float* __restrict__ in, int mod) {
    int row = blockIdx.x * 8 + (threadIdx.x >> 5);
    if (row >= NU) return;
    float* p = g_xm + (size_t)mod * NN * D + (size_t)row * D;
    int lane = threadIdx.x & 31;
    float a = in[(size_t)row * 64 + lane];
    float b = in[(size_t)row * 64 + 32 + lane];
    float ss = a * a + b * b;
    #pragma unroll
    for (int o = 16; o; o >>= 1) ss += __shfl_xor_sync(0xffffffffu, ss, o);
    float inv = rsqrtf(fmaxf(ss, 1e-24f));
    p[lane]      = a * inv;
    p[32 + lane] = b * inv;
}

// g_hx slot0 = l2norm(id_emb) (NN rows).
__global__ void k_l2norm_x(const float* __restrict__ in) {
    int row = blockIdx.x * 8 + (threadIdx.x >> 5);
    if (row >= NN) return;
    int lane = threadIdx.x & 31;
    float a = in[(size_t)row * 64 + lane];
    float b = in[(size_t)row * 64 + 32 + lane];
    float ss = a * a + b * b;
    #pragma unroll
    for (int o = 16; o; o >>= 1) ss += __shfl_xor_sync(0xffffffffu, ss, o);
    float inv = rsqrtf(fmaxf(ss, 1e-24f));
    g_hx[(size_t)row * 64 + lane]      = a * inv;
    g_hx[(size_t)row * 64 + 32 + lane] = b * inv;
}

// ------------------- GAT (gather, warp per dst node) -------------------
__global__ void k_gat_node(int mod, int nNodes, int mode, float* __restrict__ out, int modoff) {
    int n = blockIdx.x * 8 + (threadIdx.x >> 5);
    if (n >= nNodes) return;
    float* xbase = g_xm + (size_t)mod * NN * D;
    int lane = threadIdx.x & 31;
    int beg = g_offG[n];
    int end = beg + g_degG[n];

    float2 xdv = *(const float2*)&xbase[(size_t)n * D + lane * 2];

    // pass 1: exp(dot) per edge, segment sum (rows unit-norm -> no max-subtract needed)
    float s = 0.f;
    for (int p = beg; p < end; p++) {
        int src = g_csrG_src[p];
        float2 v = *(const float2*)&xbase[(size_t)src * D + lane * 2];
        float dt = xdv.x * v.x + xdv.y * v.y;
        #pragma unroll
        for (int o = 16; o; o >>= 1) dt += __shfl_xor_sync(0xffffffffu, dt, o);
        float ex = __expf(dt);
        if (lane == 0) g_e[p] = ex;
        s += ex;
    }
    __syncwarp();

    float accx = 0.f, accy = 0.f;
    if (mode == 0) {
        float invs = 1.f / (s + 1e-16f);
        for (int p = beg; p < end; p++) {
            int src = g_csrG_src[p];
            float2 v = *(const float2*)&xbase[(size_t)src * D + lane * 2];
            float a = g_e[p] * invs;
            accx += a * v.x;
            accy += a * v.y;
        }
        float nx = xdv.x + accx, ny = xdv.y + accy;
        float ss = nx * nx + ny * ny;
        #pragma unroll
        for (int o = 16; o; o >>= 1) ss += __shfl_xor_sync(0xffffffffu, ss, o);
        float inv = rsqrtf(fmaxf(ss, 1e-24f));
        xbase[(size_t)n * D + lane * 2]     = nx * inv;
        xbase[(size_t)n * D + lane * 2 + 1] = ny * inv;
    } else {
        float inv2 = 1.f / (2.f * s + 1e-16f);
        float* alpha = g_alpha + (size_t)mod * E;
        for (int p = beg; p < end; p++) {
            int src = g_csrG_src[p];
            float2 v = *(const float2*)&xbase[(size_t)src * D + lane * 2];
            float a = g_e[p] * inv2;
            if (lane == 0) alpha[p] = a;
            float a2 = a + a;
            accx += a2 * v.x;
            accy += a2 * v.y;
        }
        int c = lane * 2;
        out[(size_t)n * OD + 64 + modoff + c]     = xdv.x + lrelu(accx);
        out[(size_t)n * OD + 64 + modoff + c + 1] = xdv.y + lrelu(accy);
    }
}

// Combined SAGE weight per CSR slot.
__global__ void k_weight(const float* __restrict__ conf) {
    int p = blockIdx.x * blockDim.x + threadIdx.x;
    if (p >= E) return;
    int src = g_csrG_src[p];
    float wv = g_alpha[p];
    float wt = g_alpha[E + p];
    float w = fmaxf(fmaxf(wv * conf[2 * src], wt * conf[2 * src + 1]), 0.f);
    g_wc[p] = w;
}

// SAGE gather over GAT CSR. layer 1: hx slot0 -> hx slot1; layer 2: hx slot1 -> out[:,0:64].
__global__ void k_sage_node(int layer, float* __restrict__ out) {
    int n = blockIdx.x * 8 + (threadIdx.x >> 5);
    if (n >= NN) return;
    const float* xin = g_hx + (size_t)(layer - 1) * NN * D;
    int lane = threadIdx.x & 31;
    int beg = g_offG[n];
    int cnt = g_degG[n];
    float ax = 0.f, ay = 0.f;
    for (int p = beg; p < beg + cnt; p++) {
        float w = g_wc[p];
        if (w != 0.f) {
            int src = g_csrG_src[p];
            float2 v = *(const float2*)&xin[(size_t)src * D + lane * 2];
            ax += w * v.x;
            ay += w * v.y;
        }
    }
    float invd = 1.f / fmaxf((float)cnt, 1.f);
    float hx = lrelu(ax * invd), hy = lrelu(ay * invd);
    int c = lane * 2;
    if (layer == 1) {
        g_hx[(size_t)NN * D + (size_t)n * D + c]     = hx;
        g_hx[(size_t)NN * D + (size_t)n * D + c + 1] = hy;
    } else {
        size_t b = (size_t)n * D + c;
        out[(size_t)n * OD + c]     = g_hx[b]     + g_hx[(size_t)NN * D + b]     + hx;
        out[(size_t)n * OD + c + 1] = g_hx[b + 1] + g_hx[(size_t)NN * D + b + 1] + hy;
    }
}

// ------------------- launch -------------------
extern "C" void kernel_launch(void* const* d_in, const int* in_sizes, int n_in,
                              void* d_out, int out_size) {
    const void* ei = nullptr;
    const float *v_feat = 0, *t_feat = 0, *pref_v = 0, *pref_t = 0;
    const float *W_v = 0, *b_v = 0, *W_t = 0, *b_t = 0, *id_emb = 0, *conf = 0;
    for (int i = 0; i < n_in; i++) {
        long long sz = in_sizes[i];
        const void* p = d_in[i];
        switch (sz) {
            case 2000000LL:  ei = p; break;
            case 81920000LL: v_feat = (const float*)p; break;
            case 15360000LL: t_feat = (const float*)p; break;
            case 3200000LL:  if (!pref_v) pref_v = (const float*)p; else pref_t = (const float*)p; break;
            case 131072LL:   W_v = (const float*)p; break;
            case 24576LL:    W_t = (const float*)p; break;
            case 64LL:       if (!b_v) b_v = (const float*)p; else b_t = (const float*)p; break;
            case 5760000LL:  id_emb = (const float*)p; break;
            case 180000LL:   conf = (const float*)p; break;
            default: break;
        }
    }
    float* out = (float*)d_out;

    const int B = 256;
    const int gridNodeAll = divup(NN, 8);
    const int gridNodeU   = divup(NU, 8);
    const int nScanB      = divup(NN, 1024);   // 88

    // graph construction
    k_sniff<<<1, 32>>>((const int*)ei);
    k_zero <<<divup(NN, B), B>>>();
    k_build<<<divup(E, B), B>>>(ei);
    k_scan1<<<nScanB, 1024>>>();
    k_scan2<<<1, 128>>>(nScanB);
    k_scan3<<<nScanB, 1024>>>();
    k_place<<<divup(E, B), B>>>();

    // content branches
    for (int mod = 0; mod < 2; mod++) {
        const float* feat_in = mod == 0 ? v_feat : t_feat;
        const float* W       = mod == 0 ? W_v : W_t;
        const float* bias    = mod == 0 ? b_v : b_t;
        const float* pref_in = mod == 0 ? pref_v : pref_t;
        int K = mod == 0 ? 2048 : 384;

        k_gemm_fused<<<divup(NI, 128), 256>>>(feat_in, W, bias, mod, K);
        k_l2norm_pref<<<divup(NU, 8), 256>>>(pref_in, mod);

        for (int it = 0; it < 3; it++)
            k_gat_node<<<gridNodeU, 256>>>(mod, NU, 0, nullptr, 0);

        k_gat_node<<<gridNodeAll, 256>>>(mod, NN, 1, out, mod * 64);
    }

    // SAGE weights per CSR slot
    k_weight<<<divup(E, B), B>>>(conf);

    // egcn
    k_l2norm_x<<<divup(NN, 8), 256>>>(id_emb);
    k_sage_node<<<gridNodeAll, 256>>>(1, nullptr);
    k_sage_node<<<gridNodeAll, 256>>>(2, out);
}